// round 1
// baseline (speedup 1.0000x reference)
#include <cuda_runtime.h>
#include <math.h>
#include <stdint.h>

// ---------------------------------------------------------------------------
// DetectionLoss (FCOS-style) on GB300.
// Inputs (metadata order):
//  0 boxes_xyxy   (B,L,4) f32
//  1 box_deltas   (B,L,4) f32
//  2 class_logits (B,L,C) f32
//  3 objectness   (B,L)   f32
//  4 centerness   (B,L)   f32
//  5 locations    (L,2)   f32
//  6 gt_boxes     (B,M,4) f32  [cx,cy,w,h]
//  7 gt_labels    (B,M)   i32
//  8 grid_h       scalar  i32
//  9 grid_w       scalar  i32
// Output: scalar f32 loss.
// ---------------------------------------------------------------------------

#define MAX_BM 4096
#define MAX_M  64

// accumulators: 0 obj, 1 cls, 2 ctr, 3 l1, 4 giou, 5 wsum
__device__ double g_acc[8];
__device__ int    g_best[MAX_BM];
__device__ int    g_anycand[MAX_BM];

// ---------------- math helpers -------------------------------------------

// returns sigmoid(x); sets sp = softplus(x) = log(1+exp(x)) (stable)
__device__ __forceinline__ float sigmoid_sp(float x, float& sp) {
    float e  = __expf(-fabsf(x));          // exp(-|x|) in (0,1]
    float lp = __logf(1.0f + e);           // log1p(e)
    sp = fmaxf(x, 0.0f) + lp;
    float s = __fdividef(1.0f, 1.0f + e);  // 1/(1+e)
    return (x >= 0.0f) ? s : (1.0f - s);
}

// focal term for target=0: (1-alpha)*ce*(1-p_t)^2 = 0.75*softplus(x)*p^2
__device__ __forceinline__ float focal0(float x) {
    float sp; float p = sigmoid_sp(x, sp);
    return 0.75f * sp * p * p;
}
// focal term for target=1: 0.25*softplus(-x)*(1-p)^2; softplus(-x)=softplus(x)-x
__device__ __forceinline__ float focal1(float x) {
    float sp; float p = sigmoid_sp(x, sp);
    float q = 1.0f - p;
    return 0.25f * (sp - x) * q * q;
}

__device__ __forceinline__ float blockReduceSumF(float v) {
    __shared__ float sh[32];
    int lane = threadIdx.x & 31, wid = threadIdx.x >> 5;
#pragma unroll
    for (int o = 16; o; o >>= 1) v += __shfl_down_sync(0xffffffffu, v, o);
    if (lane == 0) sh[wid] = v;
    __syncthreads();
    int nw = (blockDim.x + 31) >> 5;
    v = (threadIdx.x < nw) ? sh[threadIdx.x] : 0.0f;
    __syncthreads();   // sh reusable on next call
    if (wid == 0) {
#pragma unroll
        for (int o = 16; o; o >>= 1) v += __shfl_down_sync(0xffffffffu, v, o);
    }
    return v;  // valid on thread 0
}

// ---------------- kernel 0: zero accumulators -----------------------------

__global__ void k_init() {
    if (threadIdx.x < 8) g_acc[threadIdx.x] = 0.0;
}

// ---------------- kernel A: per-(b,m) reductions over L -------------------
// computes: any(candidate), and fallback best location:
//   best = anyInside ? argmin(dist | inside) : argmin(dist)
// argmin tie-break = lowest index (jnp.argmin first occurrence).

__global__ __launch_bounds__(256) void k_assign(
    const float* __restrict__ loc,       // (L,2)
    const float* __restrict__ gt_boxes,  // (B,M,4)
    const int* __restrict__ ghp, const int* __restrict__ gwp, int L)
{
    int bm = blockIdx.x;
    float4 gb = reinterpret_cast<const float4*>(gt_boxes)[bm];
    float cx = gb.x, cy = gb.y, w = gb.z, h = gb.w;
    float x1 = cx - w * 0.5f, y1 = cy - h * 0.5f;
    float x2 = cx + w * 0.5f, y2 = cy + h * 0.5f;
    float gw = gwp ? (float)(*gwp) : sqrtf((float)L);
    float gh = ghp ? (float)(*ghp) : sqrtf((float)L);
    float rx = 1.0f / gw, ry = 1.0f / gh;   // POS_RADIUS = 1.0

    int tid = threadIdx.x;
    bool anyc = false, anyin = false;
    float bd_in = 3.0e38f;  int bi_in = 0x7fffffff;
    float bd_all = 3.0e38f; int bi_all = 0x7fffffff;

    const float2* loc2 = reinterpret_cast<const float2*>(loc);
    for (int l = tid; l < L; l += 256) {
        float2 p = loc2[l];
        float lx = p.x, ly = p.y;
        bool inb = (lx > x1) && (ly > y1) && (lx < x2) && (ly < y2);
        float dx = lx - cx, dy = ly - cy;
        float dist = dx * dx + dy * dy;
        bool inc = (fabsf(dx) <= rx) && (fabsf(dy) <= ry);
        anyc  |= (inb && inc);
        anyin |= inb;
        if (dist < bd_all) { bd_all = dist; bi_all = l; }       // ascending l -> first wins
        if (inb && dist < bd_in) { bd_in = dist; bi_in = l; }
    }

    __shared__ float sdi[256], sda[256];
    __shared__ int   sii[256], sia[256], sfl[256];
    sdi[tid] = bd_in;  sii[tid] = bi_in;
    sda[tid] = bd_all; sia[tid] = bi_all;
    sfl[tid] = (anyc ? 1 : 0) | (anyin ? 2 : 0);
    __syncthreads();
    for (int s = 128; s > 0; s >>= 1) {
        if (tid < s) {
            float d2 = sdi[tid + s]; int i2 = sii[tid + s];
            if (d2 < sdi[tid] || (d2 == sdi[tid] && i2 < sii[tid])) { sdi[tid] = d2; sii[tid] = i2; }
            d2 = sda[tid + s]; i2 = sia[tid + s];
            if (d2 < sda[tid] || (d2 == sda[tid] && i2 < sia[tid])) { sda[tid] = d2; sia[tid] = i2; }
            sfl[tid] |= sfl[tid + s];
        }
        __syncthreads();
    }
    if (tid == 0) {
        int fl = sfl[0];
        g_anycand[bm] = fl & 1;
        g_best[bm]    = (fl & 2) ? sii[0] : sia[0];
    }
}

// ---------------- kernel B: per-location losses (except bulk cls) ---------

__global__ __launch_bounds__(256) void k_main(
    const float* __restrict__ boxes,     // (B,L,4)
    const float* __restrict__ deltas,    // (B,L,4)
    const float* __restrict__ logits,    // (B,L,C)
    const float* __restrict__ objn,      // (B,L)
    const float* __restrict__ ctrn,      // (B,L)
    const float* __restrict__ loc,       // (L,2)
    const float* __restrict__ gt_boxes,  // (B,M,4)
    const int*   __restrict__ gt_labels, // (B,M)
    const int* __restrict__ ghp, const int* __restrict__ gwp,
    int B, int M, int L, int C)
{
    int b = blockIdx.y;
    int l = blockIdx.x * blockDim.x + threadIdx.x;

    __shared__ float sx1[MAX_M], sy1[MAX_M], sx2[MAX_M], sy2[MAX_M];
    __shared__ float scx[MAX_M], scy[MAX_M], sarea[MAX_M];
    __shared__ int   slab[MAX_M], sbest[MAX_M], sany[MAX_M];

    if (threadIdx.x < M) {
        int m = threadIdx.x;
        float4 gb = reinterpret_cast<const float4*>(gt_boxes)[b * M + m];
        float cx = gb.x, cy = gb.y, w = gb.z, h = gb.w;
        sx1[m] = cx - w * 0.5f;  sy1[m] = cy - h * 0.5f;
        sx2[m] = cx + w * 0.5f;  sy2[m] = cy + h * 0.5f;
        scx[m] = cx; scy[m] = cy;
        sarea[m] = w * h;
        slab[m]  = gt_labels[b * M + m];
        sbest[m] = g_best[b * M + m];
        sany[m]  = g_anycand[b * M + m];
    }
    __syncthreads();

    float gw = gwp ? (float)(*gwp) : sqrtf((float)L);
    float gh = ghp ? (float)(*ghp) : sqrtf((float)L);
    float rx = 1.0f / gw, ry = 1.0f / gh;

    float t_obj = 0.f, t_cls = 0.f, t_ctr = 0.f, t_l1 = 0.f, t_giou = 0.f, t_w = 0.f;

    if (l < L) {
        float2 p2 = reinterpret_cast<const float2*>(loc)[l];
        float lx = p2.x, ly = p2.y;

        // assignment: min area over effective candidates, first index on ties
        int   am = -1;
        float barea = 3.0e38f;
#pragma unroll 8
        for (int m = 0; m < M; m++) {
            bool inb = (lx > sx1[m]) && (ly > sy1[m]) && (lx < sx2[m]) && (ly < sy2[m]);
            bool inc = (fabsf(lx - scx[m]) <= rx) && (fabsf(ly - scy[m]) <= ry);
            bool cand = inb && inc;
            bool eff = sany[m] ? cand : (l == sbest[m]);
            if (eff && sarea[m] < barea) { barea = sarea[m]; am = m; }
        }

        int bl = b * L + l;
        float ox = objn[bl];

        if (am >= 0) {
            // positive location
            t_obj = focal1(ox);

            float ax1 = sx1[am], ay1 = sy1[am], ax2 = sx2[am], ay2 = sy2[am];
            float lt = fmaxf(lx - ax1, 1e-6f), tt = fmaxf(ly - ay1, 1e-6f);
            float rt = fmaxf(ax2 - lx, 1e-6f), bt = fmaxf(ay2 - ly, 1e-6f);

            float hor = __fdividef(fminf(lt, rt), fmaxf(fmaxf(lt, rt), 1e-6f));
            float ver = __fdividef(fminf(tt, bt), fmaxf(fmaxf(tt, bt), 1e-6f));
            float ctr_t = sqrtf(fmaxf(hor * ver, 0.0f));
            float wgt = fmaxf(ctr_t, 0.1f);
            t_w = wgt;

            // centerness BCE: softplus(x) - x*t
            float cxv = ctrn[bl];
            float spc; (void)sigmoid_sp(cxv, spc);
            t_ctr = (spc - cxv * ctr_t) * wgt;

            // smooth L1 on deltas vs ltrb
            float4 bd = reinterpret_cast<const float4*>(deltas)[bl];
            float d0 = fabsf(bd.x - lt), d1 = fabsf(bd.y - tt);
            float d2 = fabsf(bd.z - rt), d3 = fabsf(bd.w - bt);
            float s0 = (d0 < 0.1f) ? 5.0f * d0 * d0 : d0 - 0.05f;
            float s1 = (d1 < 0.1f) ? 5.0f * d1 * d1 : d1 - 0.05f;
            float s2 = (d2 < 0.1f) ? 5.0f * d2 * d2 : d2 - 0.05f;
            float s3 = (d3 < 0.1f) ? 5.0f * d3 * d3 : d3 - 0.05f;
            t_l1 = 0.25f * (s0 + s1 + s2 + s3) * wgt;

            // GIoU vs predicted boxes
            float4 pb = reinterpret_cast<const float4*>(boxes)[bl];
            float px1 = pb.x, py1 = pb.y, px2 = pb.z, py2 = pb.w;
            float ix1 = fmaxf(px1, ax1), iy1 = fmaxf(py1, ay1);
            float ix2 = fminf(px2, ax2), iy2 = fminf(py2, ay2);
            float inter = fmaxf(ix2 - ix1, 0.0f) * fmaxf(iy2 - iy1, 0.0f);
            float ap = fmaxf(px2 - px1, 0.0f) * fmaxf(py2 - py1, 0.0f);
            float ag = fmaxf(ax2 - ax1, 0.0f) * fmaxf(ay2 - ay1, 0.0f);
            float uni = ap + ag - inter;
            float iou = __fdividef(inter, fmaxf(uni, 1e-6f));
            float hx1 = fminf(px1, ax1), hy1 = fminf(py1, ay1);
            float hx2 = fmaxf(px2, ax2), hy2 = fmaxf(py2, ay2);
            float hull = fmaxf(hx2 - hx1, 0.0f) * fmaxf(hy2 - hy1, 0.0f);
            float giou = iou - __fdividef(hull - uni, fmaxf(hull, 1e-6f));
            t_giou = (1.0f - giou) * wgt;

            // class focal correction: bulk kernel counted f0 at the labelled
            // class; true contribution is f1. Add the difference.
            float xl = logits[(size_t)bl * C + slab[am]];
            t_cls = focal1(xl) - focal0(xl);
        } else {
            t_obj = focal0(ox);
        }
    }

    float r;
    r = blockReduceSumF(t_obj);  if (threadIdx.x == 0) atomicAdd(&g_acc[0], (double)r);
    r = blockReduceSumF(t_cls);  if (threadIdx.x == 0) atomicAdd(&g_acc[1], (double)r);
    r = blockReduceSumF(t_ctr);  if (threadIdx.x == 0) atomicAdd(&g_acc[2], (double)r);
    r = blockReduceSumF(t_l1);   if (threadIdx.x == 0) atomicAdd(&g_acc[3], (double)r);
    r = blockReduceSumF(t_giou); if (threadIdx.x == 0) atomicAdd(&g_acc[4], (double)r);
    r = blockReduceSumF(t_w);    if (threadIdx.x == 0) atomicAdd(&g_acc[5], (double)r);
}

// ---------------- kernel C: bulk class focal (target=0 term), streamed ----

__global__ __launch_bounds__(256) void k_cls(
    const float* __restrict__ logits, long long total)
{
    long long n4 = total >> 2;
    const float4* lg4 = reinterpret_cast<const float4*>(logits);
    float acc = 0.0f;
    long long stride = (long long)gridDim.x * blockDim.x;
    for (long long i = (long long)blockIdx.x * blockDim.x + threadIdx.x; i < n4; i += stride) {
        float4 v = lg4[i];
        acc += focal0(v.x) + focal0(v.y) + focal0(v.z) + focal0(v.w);
    }
    // scalar tail (none for C=80, but safe)
    if (blockIdx.x == 0 && threadIdx.x == 0) {
        for (long long i = n4 << 2; i < total; i++) acc += focal0(logits[i]);
    }
    float r = blockReduceSumF(acc);
    if (threadIdx.x == 0) atomicAdd(&g_acc[1], (double)r);
}

// ---------------- kernel D: combine ---------------------------------------

__global__ void k_final(float* out, int B, int L, int C) {
    double nBL  = (double)B * (double)L;
    double nBLC = nBL * (double)C;
    double wsum = g_acc[5];
    double inv_w = (wsum != 0.0) ? (1.0 / wsum) : 0.0;
    double loss = 1.0 * g_acc[0] / nBL          // OBJ_W * loss_obj
                + 1.5 * g_acc[1] / nBLC         // CLS_W * loss_cls
                + 0.5 * g_acc[2] * inv_w        // CTR_W * loss_ctr
                + 5.0 * g_acc[3] * inv_w        // BOX_W * loss_l1
                + 2.0 * g_acc[4] * inv_w;       // GIOU_W * loss_giou
    out[0] = (float)loss;
}

// ---------------- launch ---------------------------------------------------

extern "C" void kernel_launch(void* const* d_in, const int* in_sizes, int n_in,
                              void* d_out, int out_size)
{
    const float* boxes  = (const float*)d_in[0];
    const float* deltas = (const float*)d_in[1];
    const float* logits = (const float*)d_in[2];
    const float* objn   = (const float*)d_in[3];
    const float* ctrn   = (const float*)d_in[4];
    const float* loc    = (const float*)d_in[5];
    const float* gtb    = (const float*)d_in[6];
    const int*   gtl    = (const int*)d_in[7];
    const int*   ghp    = (n_in > 8) ? (const int*)d_in[8] : nullptr;
    const int*   gwp    = (n_in > 9) ? (const int*)d_in[9] : nullptr;

    int L = in_sizes[5] / 2;
    int B = in_sizes[3] / L;
    int M = in_sizes[7] / B;
    int C = in_sizes[2] / in_sizes[3];

    k_init<<<1, 32>>>();
    k_assign<<<B * M, 256>>>(loc, gtb, ghp, gwp, L);
    dim3 gmain((L + 255) / 256, B);
    k_main<<<gmain, 256>>>(boxes, deltas, logits, objn, ctrn, loc, gtb, gtl,
                           ghp, gwp, B, M, L, C);
    k_cls<<<2368, 256>>>(logits, (long long)in_sizes[2]);
    k_final<<<1, 1>>>((float*)d_out, B, L, C);
}

// round 2
// speedup vs baseline: 1.1404x; 1.1404x over previous
#include <cuda_runtime.h>
#include <math.h>
#include <stdint.h>

// ---------------------------------------------------------------------------
// DetectionLoss (FCOS-style) on GB300 — Round 2: fused 3-launch version.
//  launch 1: k_assign  (also zeroes accumulators from block 0)
//  launch 2: k_fused   (per-location losses + bulk class-focal stream)
//  launch 3: k_final
// ---------------------------------------------------------------------------

#define MAX_BM 4096
#define MAX_M  64

// accumulators: 0 obj, 1 cls, 2 ctr, 3 l1, 4 giou, 5 wsum
__device__ double g_acc[8];
__device__ int    g_best[MAX_BM];
__device__ int    g_anycand[MAX_BM];

// ---------------- math helpers -------------------------------------------

// returns sigmoid(x); sets sp = softplus(x) = log(1+exp(x)) (stable)
__device__ __forceinline__ float sigmoid_sp(float x, float& sp) {
    float e  = __expf(-fabsf(x));          // exp(-|x|) in (0,1]
    float lp = __logf(1.0f + e);           // log1p(e)
    sp = fmaxf(x, 0.0f) + lp;
    float s = __fdividef(1.0f, 1.0f + e);  // 1/(1+e)
    return (x >= 0.0f) ? s : (1.0f - s);
}

// focal term for target=0: 0.75*softplus(x)*sigmoid(x)^2
__device__ __forceinline__ float focal0(float x) {
    float sp; float p = sigmoid_sp(x, sp);
    return 0.75f * sp * p * p;
}
// focal term for target=1: 0.25*softplus(-x)*(1-p)^2
__device__ __forceinline__ float focal1(float x) {
    float sp; float p = sigmoid_sp(x, sp);
    float q = 1.0f - p;
    return 0.25f * (sp - x) * q * q;
}

__device__ __forceinline__ float blockReduceSumF(float v) {
    __shared__ float sh[32];
    int lane = threadIdx.x & 31, wid = threadIdx.x >> 5;
#pragma unroll
    for (int o = 16; o; o >>= 1) v += __shfl_down_sync(0xffffffffu, v, o);
    if (lane == 0) sh[wid] = v;
    __syncthreads();
    int nw = (blockDim.x + 31) >> 5;
    v = (threadIdx.x < nw) ? sh[threadIdx.x] : 0.0f;
    __syncthreads();
    if (wid == 0) {
#pragma unroll
        for (int o = 16; o; o >>= 1) v += __shfl_down_sync(0xffffffffu, v, o);
    }
    return v;  // valid on thread 0
}

// ---------------- kernel A: per-(b,m) reductions over L -------------------

__global__ __launch_bounds__(256) void k_assign(
    const float* __restrict__ loc,       // (L,2)
    const float* __restrict__ gt_boxes,  // (B,M,4)
    const int* __restrict__ ghp, const int* __restrict__ gwp, int L)
{
    int bm = blockIdx.x;
    if (bm == 0 && threadIdx.x < 8) g_acc[threadIdx.x] = 0.0;  // init accumulators

    float4 gb = reinterpret_cast<const float4*>(gt_boxes)[bm];
    float cx = gb.x, cy = gb.y, w = gb.z, h = gb.w;
    float x1 = cx - w * 0.5f, y1 = cy - h * 0.5f;
    float x2 = cx + w * 0.5f, y2 = cy + h * 0.5f;
    float gw = gwp ? (float)(*gwp) : sqrtf((float)L);
    float gh = ghp ? (float)(*ghp) : sqrtf((float)L);
    float rx = 1.0f / gw, ry = 1.0f / gh;   // POS_RADIUS = 1.0

    int tid = threadIdx.x;
    bool anyc = false, anyin = false;
    float bd_in = 3.0e38f;  int bi_in = 0x7fffffff;
    float bd_all = 3.0e38f; int bi_all = 0x7fffffff;

    const float2* loc2 = reinterpret_cast<const float2*>(loc);
    for (int l = tid; l < L; l += 256) {
        float2 p = loc2[l];
        float lx = p.x, ly = p.y;
        bool inb = (lx > x1) && (ly > y1) && (lx < x2) && (ly < y2);
        float dx = lx - cx, dy = ly - cy;
        float dist = dx * dx + dy * dy;
        bool inc = (fabsf(dx) <= rx) && (fabsf(dy) <= ry);
        anyc  |= (inb && inc);
        anyin |= inb;
        if (dist < bd_all) { bd_all = dist; bi_all = l; }   // ascending l -> first wins
        if (inb && dist < bd_in) { bd_in = dist; bi_in = l; }
    }

    __shared__ float sdi[256], sda[256];
    __shared__ int   sii[256], sia[256], sfl[256];
    sdi[tid] = bd_in;  sii[tid] = bi_in;
    sda[tid] = bd_all; sia[tid] = bi_all;
    sfl[tid] = (anyc ? 1 : 0) | (anyin ? 2 : 0);
    __syncthreads();
    for (int s = 128; s > 0; s >>= 1) {
        if (tid < s) {
            float d2 = sdi[tid + s]; int i2 = sii[tid + s];
            if (d2 < sdi[tid] || (d2 == sdi[tid] && i2 < sii[tid])) { sdi[tid] = d2; sii[tid] = i2; }
            d2 = sda[tid + s]; i2 = sia[tid + s];
            if (d2 < sda[tid] || (d2 == sda[tid] && i2 < sia[tid])) { sda[tid] = d2; sia[tid] = i2; }
            sfl[tid] |= sfl[tid + s];
        }
        __syncthreads();
    }
    if (tid == 0) {
        int fl = sfl[0];
        g_anycand[bm] = fl & 1;
        g_best[bm]    = (fl & 2) ? sii[0] : sia[0];
    }
}

// ---------------- fused kernel: per-location losses + bulk cls stream -----
// grid = (L/256, B); each block also streams its own 256xC logits slab.

__global__ __launch_bounds__(256) void k_fused(
    const float* __restrict__ boxes,     // (B,L,4)
    const float* __restrict__ deltas,    // (B,L,4)
    const float* __restrict__ logits,    // (B,L,C)
    const float* __restrict__ objn,      // (B,L)
    const float* __restrict__ ctrn,      // (B,L)
    const float* __restrict__ loc,       // (L,2)
    const float* __restrict__ gt_boxes,  // (B,M,4)
    const int*   __restrict__ gt_labels, // (B,M)
    const int* __restrict__ ghp, const int* __restrict__ gwp,
    int B, int M, int L, int C)
{
    int b  = blockIdx.y;
    int l0 = blockIdx.x * 256;
    int l  = l0 + threadIdx.x;

    __shared__ float sx1[MAX_M], sy1[MAX_M], sx2[MAX_M], sy2[MAX_M];
    __shared__ float scx[MAX_M], scy[MAX_M], sarea[MAX_M];
    __shared__ int   slab[MAX_M], sbest[MAX_M], sany[MAX_M];

    if (threadIdx.x < M) {
        int m = threadIdx.x;
        float4 gb = reinterpret_cast<const float4*>(gt_boxes)[b * M + m];
        float cx = gb.x, cy = gb.y, w = gb.z, h = gb.w;
        sx1[m] = cx - w * 0.5f;  sy1[m] = cy - h * 0.5f;
        sx2[m] = cx + w * 0.5f;  sy2[m] = cy + h * 0.5f;
        scx[m] = cx; scy[m] = cy;
        sarea[m] = w * h;
        slab[m]  = gt_labels[b * M + m];
        sbest[m] = g_best[b * M + m];
        sany[m]  = g_anycand[b * M + m];
    }
    __syncthreads();

    float gw = gwp ? (float)(*gwp) : sqrtf((float)L);
    float gh = ghp ? (float)(*ghp) : sqrtf((float)L);
    float rx = 1.0f / gw, ry = 1.0f / gh;

    float t_obj = 0.f, t_cls = 0.f, t_ctr = 0.f, t_l1 = 0.f, t_giou = 0.f, t_w = 0.f;

    if (l < L) {
        float2 p2 = reinterpret_cast<const float2*>(loc)[l];
        float lx = p2.x, ly = p2.y;

        int   am = -1;
        float barea = 3.0e38f;
#pragma unroll 8
        for (int m = 0; m < M; m++) {
            bool inb = (lx > sx1[m]) && (ly > sy1[m]) && (lx < sx2[m]) && (ly < sy2[m]);
            bool inc = (fabsf(lx - scx[m]) <= rx) && (fabsf(ly - scy[m]) <= ry);
            bool cand = inb && inc;
            bool eff = sany[m] ? cand : (l == sbest[m]);
            if (eff && sarea[m] < barea) { barea = sarea[m]; am = m; }
        }

        int bl = b * L + l;
        float ox = objn[bl];

        if (am >= 0) {
            t_obj = focal1(ox);

            float ax1 = sx1[am], ay1 = sy1[am], ax2 = sx2[am], ay2 = sy2[am];
            float lt = fmaxf(lx - ax1, 1e-6f), tt = fmaxf(ly - ay1, 1e-6f);
            float rt = fmaxf(ax2 - lx, 1e-6f), bt = fmaxf(ay2 - ly, 1e-6f);

            float hor = __fdividef(fminf(lt, rt), fmaxf(fmaxf(lt, rt), 1e-6f));
            float ver = __fdividef(fminf(tt, bt), fmaxf(fmaxf(tt, bt), 1e-6f));
            float ctr_t = sqrtf(fmaxf(hor * ver, 0.0f));
            float wgt = fmaxf(ctr_t, 0.1f);
            t_w = wgt;

            float cxv = ctrn[bl];
            float spc; (void)sigmoid_sp(cxv, spc);
            t_ctr = (spc - cxv * ctr_t) * wgt;

            float4 bd = reinterpret_cast<const float4*>(deltas)[bl];
            float d0 = fabsf(bd.x - lt), d1 = fabsf(bd.y - tt);
            float d2 = fabsf(bd.z - rt), d3 = fabsf(bd.w - bt);
            float s0 = (d0 < 0.1f) ? 5.0f * d0 * d0 : d0 - 0.05f;
            float s1 = (d1 < 0.1f) ? 5.0f * d1 * d1 : d1 - 0.05f;
            float s2 = (d2 < 0.1f) ? 5.0f * d2 * d2 : d2 - 0.05f;
            float s3 = (d3 < 0.1f) ? 5.0f * d3 * d3 : d3 - 0.05f;
            t_l1 = 0.25f * (s0 + s1 + s2 + s3) * wgt;

            float4 pb = reinterpret_cast<const float4*>(boxes)[bl];
            float px1 = pb.x, py1 = pb.y, px2 = pb.z, py2 = pb.w;
            float ix1 = fmaxf(px1, ax1), iy1 = fmaxf(py1, ay1);
            float ix2 = fminf(px2, ax2), iy2 = fminf(py2, ay2);
            float inter = fmaxf(ix2 - ix1, 0.0f) * fmaxf(iy2 - iy1, 0.0f);
            float ap = fmaxf(px2 - px1, 0.0f) * fmaxf(py2 - py1, 0.0f);
            float ag = fmaxf(ax2 - ax1, 0.0f) * fmaxf(ay2 - ay1, 0.0f);
            float uni = ap + ag - inter;
            float iou = __fdividef(inter, fmaxf(uni, 1e-6f));
            float hx1 = fminf(px1, ax1), hy1 = fminf(py1, ay1);
            float hx2 = fmaxf(px2, ax2), hy2 = fmaxf(py2, ay2);
            float hull = fmaxf(hx2 - hx1, 0.0f) * fmaxf(hy2 - hy1, 0.0f);
            float giou = iou - __fdividef(hull - uni, fmaxf(hull, 1e-6f));
            t_giou = (1.0f - giou) * wgt;

            // class focal correction at the labelled class
            float xl = logits[(size_t)bl * C + slab[am]];
            t_cls = focal1(xl) - focal0(xl);
        } else {
            t_obj = focal0(ox);
        }
    }

    // ---- bulk class-focal stream over this block's logits slab -----------
    // slab = rows [b*L + l0, b*L + l0 + 256) x C floats, contiguous.
    {
        int rows = min(256, L - l0);
        long long base  = ((long long)b * L + l0) * C;      // float index
        long long nflt  = (long long)rows * C;
        // float4 path (C=80 -> always 16B-aligned rows; base*4 bytes aligned)
        if (((base & 3) == 0) && ((nflt & 3) == 0)) {
            const float4* p4 = reinterpret_cast<const float4*>(logits + base);
            int n4 = (int)(nflt >> 2);                       // 5120 for full block
#pragma unroll 4
            for (int i = threadIdx.x; i < n4; i += 256) {
                float4 v = p4[i];
                t_cls += focal0(v.x) + focal0(v.y) + focal0(v.z) + focal0(v.w);
            }
        } else {
            for (long long i = threadIdx.x; i < nflt; i += 256)
                t_cls += focal0(logits[base + i]);
        }
    }

    float r;
    r = blockReduceSumF(t_obj);  if (threadIdx.x == 0) atomicAdd(&g_acc[0], (double)r);
    r = blockReduceSumF(t_cls);  if (threadIdx.x == 0) atomicAdd(&g_acc[1], (double)r);
    r = blockReduceSumF(t_ctr);  if (threadIdx.x == 0) atomicAdd(&g_acc[2], (double)r);
    r = blockReduceSumF(t_l1);   if (threadIdx.x == 0) atomicAdd(&g_acc[3], (double)r);
    r = blockReduceSumF(t_giou); if (threadIdx.x == 0) atomicAdd(&g_acc[4], (double)r);
    r = blockReduceSumF(t_w);    if (threadIdx.x == 0) atomicAdd(&g_acc[5], (double)r);
}

// ---------------- kernel: combine -----------------------------------------

__global__ void k_final(float* out, int B, int L, int C) {
    double nBL  = (double)B * (double)L;
    double nBLC = nBL * (double)C;
    double wsum = g_acc[5];
    double inv_w = (wsum != 0.0) ? (1.0 / wsum) : 0.0;
    double loss = 1.0 * g_acc[0] / nBL
                + 1.5 * g_acc[1] / nBLC
                + 0.5 * g_acc[2] * inv_w
                + 5.0 * g_acc[3] * inv_w
                + 2.0 * g_acc[4] * inv_w;
    out[0] = (float)loss;
}

// ---------------- launch ---------------------------------------------------

extern "C" void kernel_launch(void* const* d_in, const int* in_sizes, int n_in,
                              void* d_out, int out_size)
{
    const float* boxes  = (const float*)d_in[0];
    const float* deltas = (const float*)d_in[1];
    const float* logits = (const float*)d_in[2];
    const float* objn   = (const float*)d_in[3];
    const float* ctrn   = (const float*)d_in[4];
    const float* loc    = (const float*)d_in[5];
    const float* gtb    = (const float*)d_in[6];
    const int*   gtl    = (const int*)d_in[7];
    const int*   ghp    = (n_in > 8) ? (const int*)d_in[8] : nullptr;
    const int*   gwp    = (n_in > 9) ? (const int*)d_in[9] : nullptr;

    int L = in_sizes[5] / 2;
    int B = in_sizes[3] / L;
    int M = in_sizes[7] / B;
    int C = in_sizes[2] / in_sizes[3];

    k_assign<<<B * M, 256>>>(loc, gtb, ghp, gwp, L);
    dim3 gmain((L + 255) / 256, B);
    k_fused<<<gmain, 256>>>(boxes, deltas, logits, objn, ctrn, loc, gtb, gtl,
                            ghp, gwp, B, M, L, C);
    k_final<<<1, 1>>>((float*)d_out, B, L, C);
}

// round 3
// speedup vs baseline: 1.1894x; 1.0429x over previous
#include <cuda_runtime.h>
#include <math.h>
#include <stdint.h>

// ---------------------------------------------------------------------------
// DetectionLoss (FCOS-style) on GB300 — Round 3.
//  launch 1: k_verify  (bitwise-verify locations == regular grid; zero accs)
//  launch 2: k_assign2 (analytic per-(b,m) assignment; generic fallback)
//  launch 3: k_fused   (per-location losses + bulk class-focal stream)
//  launch 4: k_final
// ---------------------------------------------------------------------------

#define MAX_BM 4096
#define MAX_M  64
#define MAX_VB 4096

// accumulators: 0 obj, 1 cls, 2 ctr, 3 l1, 4 giou, 5 wsum
__device__ double g_acc[8];
__device__ int    g_best[MAX_BM];
__device__ int    g_anycand[MAX_BM];
__device__ int    g_verify[MAX_VB];

// ---------------- math helpers -------------------------------------------

// returns sigmoid(x); sets sp = softplus(x). Uses 2 MUFU (exp, log);
// the reciprocal runs on the FMA pipe (quadratic seed + 2 Newton).
__device__ __forceinline__ float sigmoid_sp(float x, float& sp) {
    float e = __expf(-fabsf(x));             // MUFU #1, e in (0,1]
    float u = 1.0f + e;                      // u in (1,2]
    // 1/u: quadratic interp seed (rel err ~6e-2) + 2 NR -> ~1e-5 rel
    float y = fmaf(fmaf(0.33333334f, u, -1.5f), u, 2.1666667f);
    y = y * fmaf(-u, y, 2.0f);
    y = y * fmaf(-u, y, 2.0f);
    sp = fmaxf(x, 0.0f) + __logf(u);         // MUFU #2
    return (x >= 0.0f) ? y : (1.0f - y);
}

// focal term for target=0: 0.75*softplus(x)*sigmoid(x)^2
__device__ __forceinline__ float focal0(float x) {
    float sp; float p = sigmoid_sp(x, sp);
    return 0.75f * sp * p * p;
}
// focal term for target=1: 0.25*softplus(-x)*(1-p)^2
__device__ __forceinline__ float focal1(float x) {
    float sp; float p = sigmoid_sp(x, sp);
    float q = 1.0f - p;
    return 0.25f * (sp - x) * q * q;
}

__device__ __forceinline__ float blockReduceSumF(float v) {
    __shared__ float sh[32];
    int lane = threadIdx.x & 31, wid = threadIdx.x >> 5;
#pragma unroll
    for (int o = 16; o; o >>= 1) v += __shfl_down_sync(0xffffffffu, v, o);
    if (lane == 0) sh[wid] = v;
    __syncthreads();
    int nw = (blockDim.x + 31) >> 5;
    v = (threadIdx.x < nw) ? sh[threadIdx.x] : 0.0f;
    __syncthreads();
    if (wid == 0) {
#pragma unroll
        for (int o = 16; o; o >>= 1) v += __shfl_down_sync(0xffffffffu, v, o);
    }
    return v;  // valid on thread 0
}

// grid coordinate, must match reference construction bitwise:
// (i + 0.5f) / N with rn division.
__device__ __forceinline__ float gcoord(int i, float fN) {
    return __fdiv_rn((float)i + 0.5f, fN);
}

// ---------------- kernel V: verify regular grid + zero accumulators -------

__global__ __launch_bounds__(256) void k_verify(
    const float* __restrict__ loc,
    const int* __restrict__ ghp, const int* __restrict__ gwp, int L)
{
    if (blockIdx.x == 0 && threadIdx.x < 8) g_acc[threadIdx.x] = 0.0;

    int ok = 1;
    if (ghp == nullptr || gwp == nullptr) {
        ok = 0;
    } else {
        int W = *gwp, H = *ghp;
        float fW = (float)W, fH = (float)H;
        int l = blockIdx.x * 256 + threadIdx.x;
        if (l < L) {
            if (W <= 0 || H <= 0 || (long long)W * H != L) {
                ok = 0;
            } else {
                int x = l % W, y = l / W;
                float2 p = reinterpret_cast<const float2*>(loc)[l];
                ok = (p.x == gcoord(x, fW)) && (p.y == gcoord(y, fH));
            }
        }
    }
    // block AND-reduce
    __shared__ int sok[256];
    sok[threadIdx.x] = ok;
    __syncthreads();
    for (int s = 128; s > 0; s >>= 1) {
        if (threadIdx.x < s) sok[threadIdx.x] &= sok[threadIdx.x + s];
        __syncthreads();
    }
    if (threadIdx.x == 0 && blockIdx.x < MAX_VB) g_verify[blockIdx.x] = sok[0];
}

// ---------------- kernel A: per-(b,m) assignment ---------------------------
// one thread per (b,m). If grid verified: analytic (O(1)). Else: full scan.

__global__ __launch_bounds__(64) void k_assign2(
    const float* __restrict__ loc,
    const float* __restrict__ gt_boxes,  // (B,M,4) cx,cy,w,h
    const int* __restrict__ ghp, const int* __restrict__ gwp,
    int L, int BM, int nvb)
{
    // reduce verify flags (uniform broadcast loads)
    int gok = 1;
    for (int k = 0; k < nvb; k++) gok &= g_verify[k];

    int bm = blockIdx.x * 64 + threadIdx.x;
    if (bm >= BM) return;

    float4 gb = reinterpret_cast<const float4*>(gt_boxes)[bm];
    float cx = gb.x, cy = gb.y, w = gb.z, h = gb.w;
    float x1 = cx - w * 0.5f, y1 = cy - h * 0.5f;
    float x2 = cx + w * 0.5f, y2 = cy + h * 0.5f;

    int Wg, Hg;
    if (gwp && ghp) { Wg = *gwp; Hg = *ghp; }
    else { Wg = (int)(sqrtf((float)L) + 0.5f); Hg = Wg; }
    float fW = (float)Wg, fH = (float)Hg;
    float rx = 1.0f / fW, ry = 1.0f / fH;   // POS_RADIUS = 1.0

    if (gok) {
        int W = Wg, H = Hg;
        // ---- exact index ranges for strict inside-box conditions ----
        // smallest i in [0,W] with gx(i) > x1
        int ilo = (int)floorf(x1 * fW - 0.5f) + 1;
        ilo = max(0, min(ilo, W));
        while (ilo > 0 && gcoord(ilo - 1, fW) > x1) ilo--;
        while (ilo < W && !(gcoord(ilo, fW) > x1)) ilo++;
        // largest i in [-1,W-1] with gx(i) < x2
        int ihi = (int)ceilf(x2 * fW - 0.5f) - 1;
        ihi = max(-1, min(ihi, W - 1));
        while (ihi < W - 1 && gcoord(ihi + 1, fW) < x2) ihi++;
        while (ihi >= 0 && !(gcoord(ihi, fW) < x2)) ihi--;
        // same for j
        int jlo = (int)floorf(y1 * fH - 0.5f) + 1;
        jlo = max(0, min(jlo, H));
        while (jlo > 0 && gcoord(jlo - 1, fH) > y1) jlo--;
        while (jlo < H && !(gcoord(jlo, fH) > y1)) jlo++;
        int jhi = (int)ceilf(y2 * fH - 0.5f) - 1;
        jhi = max(-1, min(jhi, H - 1));
        while (jhi < H - 1 && gcoord(jhi + 1, fH) < y2) jhi++;
        while (jhi >= 0 && !(gcoord(jhi, fH) < y2)) jhi--;

        bool anyin = (ilo <= ihi) && (jlo <= jhi);

        // ---- any-candidate: separable, window near center (rx*W == 1) ----
        int icg = (int)floorf(cx * fW - 0.5f);
        int jcg = (int)floorf(cy * fH - 0.5f);
        bool anyx = false, anyy = false;
        if (anyin) {
            for (int i = max(ilo, icg - 3); i <= min(ihi, icg + 3); i++)
                anyx |= (fabsf(gcoord(i, fW) - cx) <= rx);
            for (int j = max(jlo, jcg - 3); j <= min(jhi, jcg + 3); j++)
                anyy |= (fabsf(gcoord(j, fH) - cy) <= ry);
        }
        bool anyc = anyin && anyx && anyy;

        // ---- best fallback location: argmin dist (inside rect if anyin) --
        int ailo, aihi, ajlo, ajhi;
        if (anyin) { ailo = ilo; aihi = ihi; ajlo = jlo; ajhi = jhi; }
        else       { ailo = 0;   aihi = W-1; ajlo = 0;   ajhi = H-1; }
        int ic = max(ailo, min(icg, aihi));
        int jc = max(ajlo, min(jcg, ajhi));
        int ii0 = max(ailo, ic - 2), ii1 = min(aihi, ic + 2);
        int jj0 = max(ajlo, jc - 2), jj1 = min(ajhi, jc + 2);
        unsigned long long bk = ~0ull;
        for (int j = jj0; j <= jj1; j++) {
            float dy = gcoord(j, fH) - cy;
            float dy2 = __fmul_rn(dy, dy);
            for (int i = ii0; i <= ii1; i++) {
                float dx = gcoord(i, fW) - cx;
                float dist = __fadd_rn(__fmul_rn(dx, dx), dy2);
                unsigned long long key =
                    ((unsigned long long)__float_as_uint(dist) << 32) |
                    (unsigned int)(j * W + i);
                bk = min(bk, key);
            }
        }
        g_anycand[bm] = anyc ? 1 : 0;
        g_best[bm]    = (int)(bk & 0xffffffffu);
    } else {
        // ---- generic fallback: serial scan (correct, slow, never hot) ----
        bool anyc = false, anyin = false;
        float bd_in = 3.0e38f;  int bi_in = 0;
        float bd_all = 3.0e38f; int bi_all = 0;
        const float2* loc2 = reinterpret_cast<const float2*>(loc);
        for (int l = 0; l < L; l++) {
            float2 p = loc2[l];
            float lx = p.x, ly = p.y;
            bool inb = (lx > x1) && (ly > y1) && (lx < x2) && (ly < y2);
            float dx = lx - cx, dy = ly - cy;
            float dist = __fadd_rn(__fmul_rn(dx, dx), __fmul_rn(dy, dy));
            bool inc = (fabsf(dx) <= rx) && (fabsf(dy) <= ry);
            anyc  |= (inb && inc);
            anyin |= inb;
            if (dist < bd_all) { bd_all = dist; bi_all = l; }
            if (inb && dist < bd_in) { bd_in = dist; bi_in = l; }
        }
        g_anycand[bm] = anyc ? 1 : 0;
        g_best[bm]    = anyin ? bi_in : bi_all;
    }
}

// ---------------- fused kernel: per-location losses + bulk cls stream -----

__global__ __launch_bounds__(256) void k_fused(
    const float* __restrict__ boxes,     // (B,L,4)
    const float* __restrict__ deltas,    // (B,L,4)
    const float* __restrict__ logits,    // (B,L,C)
    const float* __restrict__ objn,      // (B,L)
    const float* __restrict__ ctrn,      // (B,L)
    const float* __restrict__ loc,       // (L,2)
    const float* __restrict__ gt_boxes,  // (B,M,4)
    const int*   __restrict__ gt_labels, // (B,M)
    const int* __restrict__ ghp, const int* __restrict__ gwp,
    int B, int M, int L, int C)
{
    int b  = blockIdx.y;
    int l0 = blockIdx.x * 256;
    int l  = l0 + threadIdx.x;

    __shared__ float sx1[MAX_M], sy1[MAX_M], sx2[MAX_M], sy2[MAX_M];
    __shared__ float scx[MAX_M], scy[MAX_M], sarea[MAX_M];
    __shared__ int   slab[MAX_M], sbest[MAX_M], sany[MAX_M];

    if (threadIdx.x < M) {
        int m = threadIdx.x;
        float4 gb = reinterpret_cast<const float4*>(gt_boxes)[b * M + m];
        float cx = gb.x, cy = gb.y, w = gb.z, h = gb.w;
        sx1[m] = cx - w * 0.5f;  sy1[m] = cy - h * 0.5f;
        sx2[m] = cx + w * 0.5f;  sy2[m] = cy + h * 0.5f;
        scx[m] = cx; scy[m] = cy;
        sarea[m] = w * h;
        slab[m]  = gt_labels[b * M + m];
        sbest[m] = g_best[b * M + m];
        sany[m]  = g_anycand[b * M + m];
    }
    __syncthreads();

    float gw = gwp ? (float)(*gwp) : sqrtf((float)L);
    float gh = ghp ? (float)(*ghp) : sqrtf((float)L);
    float rx = 1.0f / gw, ry = 1.0f / gh;

    float t_obj = 0.f, t_cls = 0.f, t_ctr = 0.f, t_l1 = 0.f, t_giou = 0.f, t_w = 0.f;

    if (l < L) {
        float2 p2 = reinterpret_cast<const float2*>(loc)[l];
        float lx = p2.x, ly = p2.y;

        int   am = -1;
        float barea = 3.0e38f;
#pragma unroll 8
        for (int m = 0; m < M; m++) {
            bool inb = (lx > sx1[m]) && (ly > sy1[m]) && (lx < sx2[m]) && (ly < sy2[m]);
            bool inc = (fabsf(lx - scx[m]) <= rx) && (fabsf(ly - scy[m]) <= ry);
            bool cand = inb && inc;
            bool eff = sany[m] ? cand : (l == sbest[m]);
            if (eff && sarea[m] < barea) { barea = sarea[m]; am = m; }
        }

        int bl = b * L + l;
        float ox = objn[bl];

        if (am >= 0) {
            t_obj = focal1(ox);

            float ax1 = sx1[am], ay1 = sy1[am], ax2 = sx2[am], ay2 = sy2[am];
            float lt = fmaxf(lx - ax1, 1e-6f), tt = fmaxf(ly - ay1, 1e-6f);
            float rt = fmaxf(ax2 - lx, 1e-6f), bt = fmaxf(ay2 - ly, 1e-6f);

            float hor = __fdividef(fminf(lt, rt), fmaxf(fmaxf(lt, rt), 1e-6f));
            float ver = __fdividef(fminf(tt, bt), fmaxf(fmaxf(tt, bt), 1e-6f));
            float ctr_t = sqrtf(fmaxf(hor * ver, 0.0f));
            float wgt = fmaxf(ctr_t, 0.1f);
            t_w = wgt;

            float cxv = ctrn[bl];
            float spc; (void)sigmoid_sp(cxv, spc);
            t_ctr = (spc - cxv * ctr_t) * wgt;

            float4 bd = reinterpret_cast<const float4*>(deltas)[bl];
            float d0 = fabsf(bd.x - lt), d1 = fabsf(bd.y - tt);
            float d2 = fabsf(bd.z - rt), d3 = fabsf(bd.w - bt);
            float s0 = (d0 < 0.1f) ? 5.0f * d0 * d0 : d0 - 0.05f;
            float s1 = (d1 < 0.1f) ? 5.0f * d1 * d1 : d1 - 0.05f;
            float s2 = (d2 < 0.1f) ? 5.0f * d2 * d2 : d2 - 0.05f;
            float s3 = (d3 < 0.1f) ? 5.0f * d3 * d3 : d3 - 0.05f;
            t_l1 = 0.25f * (s0 + s1 + s2 + s3) * wgt;

            float4 pb = reinterpret_cast<const float4*>(boxes)[bl];
            float px1 = pb.x, py1 = pb.y, px2 = pb.z, py2 = pb.w;
            float ix1 = fmaxf(px1, ax1), iy1 = fmaxf(py1, ay1);
            float ix2 = fminf(px2, ax2), iy2 = fminf(py2, ay2);
            float inter = fmaxf(ix2 - ix1, 0.0f) * fmaxf(iy2 - iy1, 0.0f);
            float ap = fmaxf(px2 - px1, 0.0f) * fmaxf(py2 - py1, 0.0f);
            float ag = fmaxf(ax2 - ax1, 0.0f) * fmaxf(ay2 - ay1, 0.0f);
            float uni = ap + ag - inter;
            float iou = __fdividef(inter, fmaxf(uni, 1e-6f));
            float hx1 = fminf(px1, ax1), hy1 = fminf(py1, ay1);
            float hx2 = fmaxf(px2, ax2), hy2 = fmaxf(py2, ay2);
            float hull = fmaxf(hx2 - hx1, 0.0f) * fmaxf(hy2 - hy1, 0.0f);
            float giou = iou - __fdividef(hull - uni, fmaxf(hull, 1e-6f));
            t_giou = (1.0f - giou) * wgt;

            float xl = logits[(size_t)bl * C + slab[am]];
            t_cls = focal1(xl) - focal0(xl);
        } else {
            t_obj = focal0(ox);
        }
    }

    // ---- bulk class-focal stream over this block's logits slab -----------
    {
        int rows = min(256, L - l0);
        long long base = ((long long)b * L + l0) * C;
        long long nflt = (long long)rows * C;
        if (((base & 3) == 0) && ((nflt & 3) == 0)) {
            const float4* p4 = reinterpret_cast<const float4*>(logits + base);
            int n4 = (int)(nflt >> 2);
#pragma unroll 5
            for (int i = threadIdx.x; i < n4; i += 256) {
                float4 v = p4[i];
                t_cls += focal0(v.x) + focal0(v.y) + focal0(v.z) + focal0(v.w);
            }
        } else {
            for (long long i = threadIdx.x; i < nflt; i += 256)
                t_cls += focal0(logits[base + i]);
        }
    }

    float r;
    r = blockReduceSumF(t_obj);  if (threadIdx.x == 0) atomicAdd(&g_acc[0], (double)r);
    r = blockReduceSumF(t_cls);  if (threadIdx.x == 0) atomicAdd(&g_acc[1], (double)r);
    r = blockReduceSumF(t_ctr);  if (threadIdx.x == 0) atomicAdd(&g_acc[2], (double)r);
    r = blockReduceSumF(t_l1);   if (threadIdx.x == 0) atomicAdd(&g_acc[3], (double)r);
    r = blockReduceSumF(t_giou); if (threadIdx.x == 0) atomicAdd(&g_acc[4], (double)r);
    r = blockReduceSumF(t_w);    if (threadIdx.x == 0) atomicAdd(&g_acc[5], (double)r);
}

// ---------------- kernel: combine -----------------------------------------

__global__ void k_final(float* out, int B, int L, int C) {
    double nBL  = (double)B * (double)L;
    double nBLC = nBL * (double)C;
    double wsum = g_acc[5];
    double inv_w = (wsum != 0.0) ? (1.0 / wsum) : 0.0;
    double loss = 1.0 * g_acc[0] / nBL
                + 1.5 * g_acc[1] / nBLC
                + 0.5 * g_acc[2] * inv_w
                + 5.0 * g_acc[3] * inv_w
                + 2.0 * g_acc[4] * inv_w;
    out[0] = (float)loss;
}

// ---------------- launch ---------------------------------------------------

extern "C" void kernel_launch(void* const* d_in, const int* in_sizes, int n_in,
                              void* d_out, int out_size)
{
    const float* boxes  = (const float*)d_in[0];
    const float* deltas = (const float*)d_in[1];
    const float* logits = (const float*)d_in[2];
    const float* objn   = (const float*)d_in[3];
    const float* ctrn   = (const float*)d_in[4];
    const float* loc    = (const float*)d_in[5];
    const float* gtb    = (const float*)d_in[6];
    const int*   gtl    = (const int*)d_in[7];
    const int*   ghp    = (n_in > 8) ? (const int*)d_in[8] : nullptr;
    const int*   gwp    = (n_in > 9) ? (const int*)d_in[9] : nullptr;

    int L = in_sizes[5] / 2;
    int B = in_sizes[3] / L;
    int M = in_sizes[7] / B;
    int C = in_sizes[2] / in_sizes[3];
    int BM = B * M;

    int nvb = (L + 255) / 256;
    if (nvb > MAX_VB) nvb = MAX_VB;          // (L fits for this problem)

    k_verify<<<nvb, 256>>>(loc, ghp, gwp, L);
    k_assign2<<<(BM + 63) / 64, 64>>>(loc, gtb, ghp, gwp, L, BM, nvb);
    dim3 gmain((L + 255) / 256, B);
    k_fused<<<gmain, 256>>>(boxes, deltas, logits, objn, ctrn, loc, gtb, gtl,
                            ghp, gwp, B, M, L, C);
    k_final<<<1, 1>>>((float*)d_out, B, L, C);
}